// round 2
// baseline (speedup 1.0000x reference)
#include <cuda_runtime.h>
#include <cuda_bf16.h>
#include <cstdint>

// LSTM fused cell: pre[g,b,h] = sum_k [x|h_prev][b,k]*[Wx|Rh][g,h,k] + bx[g,h]+bh[g,h]
// One GEMM M=16384, N=H=1024 (x4 gates in-register), K=2048, fused epilogue.
// TF32 mma.sync m16n8k8, RN-converted operands.

#define B_DIM 16384
#define H_DIM 1024
#define I_DIM 1024
#define HI (1024 * 1024)
#define BH (16384 * 1024)

#define BM 128          // CTA M tile
#define BN 32           // CTA N tile (per gate)
#define BK 32           // K tile
#define NKT 64          // 2048 / 32 K tiles
#define PITCH 36        // smem pitch (floats), pad for conflict-free frag loads

__device__ __forceinline__ uint32_t f2tf32(float f) {
    uint32_t r;
    asm("cvt.rna.tf32.f32 %0, %1;" : "=r"(r) : "f"(f));
    return r;
}

__device__ __forceinline__ void mma_tf32(float c[4], const uint32_t a[4], const uint32_t b[2]) {
    asm volatile(
        "mma.sync.aligned.m16n8k8.row.col.f32.tf32.tf32.f32 "
        "{%0,%1,%2,%3}, {%4,%5,%6,%7}, {%8,%9}, {%0,%1,%2,%3};"
        : "+f"(c[0]), "+f"(c[1]), "+f"(c[2]), "+f"(c[3])
        : "r"(a[0]), "r"(a[1]), "r"(a[2]), "r"(a[3]), "r"(b[0]), "r"(b[1]));
}

__device__ __forceinline__ float sigmoidf_fast(float x) {
    return 1.0f / (1.0f + __expf(-x));
}

__global__ void __launch_bounds__(256, 1)
lstm_fused_kernel(const float* __restrict__ x,
                  const float* __restrict__ h_prev,
                  const float* __restrict__ c_prev,
                  const float* __restrict__ Wx,
                  const float* __restrict__ bx,
                  const float* __restrict__ Rh,
                  const float* __restrict__ bh,
                  float* __restrict__ out) {
    __shared__ uint32_t As[BM][PITCH];          // [row][k] tf32
    __shared__ uint32_t Bs[4][BN][PITCH];       // [gate][n][k] tf32

    const int t = threadIdx.x;
    const int lane = t & 31;
    const int warp = t >> 5;
    const int gid = lane >> 2;    // group id (0..7)
    const int tig = lane & 3;     // thread in group (0..3)
    const int wm = warp >> 1;     // 0..3  -> 32-row slab
    const int wn = warp & 1;      // 0..1  -> 16-col slab

    const int mBase = blockIdx.y * BM;
    const int hBase = blockIdx.x * BN;

    // Staging registers for the software pipeline (raw fp32).
    float4 ra[4];
    float4 rb[4];

    // ---- prologue: load K-tile 0 ----
    {
        const float* Ap = x;                      // kt=0 -> x segment
        const float* Bp = Wx;
        const int kOff = 0;
#pragma unroll
        for (int p = 0; p < 4; ++p) {
            int idx = t + p * 256;
            int row = idx >> 3, c4 = idx & 7;
            ra[p] = *reinterpret_cast<const float4*>(
                Ap + (size_t)(mBase + row) * I_DIM + kOff + c4 * 4);
        }
#pragma unroll
        for (int p = 0; p < 4; ++p) {
            int idx = t + p * 256;
            int g = idx >> 8, n = (idx >> 3) & 31, c4 = idx & 7;
            rb[p] = *reinterpret_cast<const float4*>(
                Bp + (size_t)g * HI + (size_t)(hBase + n) * I_DIM + kOff + c4 * 4);
        }
    }

    float acc[4][2][2][4];
#pragma unroll
    for (int g = 0; g < 4; ++g)
#pragma unroll
        for (int mi = 0; mi < 2; ++mi)
#pragma unroll
            for (int ni = 0; ni < 2; ++ni)
#pragma unroll
                for (int k = 0; k < 4; ++k) acc[g][mi][ni][k] = 0.0f;

    for (int kt = 0; kt < NKT; ++kt) {
        __syncthreads();   // previous tile's smem reads done
        // ---- store staged tile to smem (fp32 -> tf32 RN) ----
#pragma unroll
        for (int p = 0; p < 4; ++p) {
            int idx = t + p * 256;
            int row = idx >> 3, c4 = idx & 7;
            As[row][c4 * 4 + 0] = f2tf32(ra[p].x);
            As[row][c4 * 4 + 1] = f2tf32(ra[p].y);
            As[row][c4 * 4 + 2] = f2tf32(ra[p].z);
            As[row][c4 * 4 + 3] = f2tf32(ra[p].w);
        }
#pragma unroll
        for (int p = 0; p < 4; ++p) {
            int idx = t + p * 256;
            int g = idx >> 8, n = (idx >> 3) & 31, c4 = idx & 7;
            Bs[g][n][c4 * 4 + 0] = f2tf32(rb[p].x);
            Bs[g][n][c4 * 4 + 1] = f2tf32(rb[p].y);
            Bs[g][n][c4 * 4 + 2] = f2tf32(rb[p].z);
            Bs[g][n][c4 * 4 + 3] = f2tf32(rb[p].w);
        }
        __syncthreads();

        // ---- prefetch next K tile (overlaps with compute below) ----
        if (kt + 1 < NKT) {
            const int ktn = kt + 1;
            const float* Ap = (ktn < 32) ? x : h_prev;
            const float* Bp = (ktn < 32) ? Wx : Rh;
            const int kOff = (ktn & 31) * BK;
#pragma unroll
            for (int p = 0; p < 4; ++p) {
                int idx = t + p * 256;
                int row = idx >> 3, c4 = idx & 7;
                ra[p] = *reinterpret_cast<const float4*>(
                    Ap + (size_t)(mBase + row) * I_DIM + kOff + c4 * 4);
            }
#pragma unroll
            for (int p = 0; p < 4; ++p) {
                int idx = t + p * 256;
                int g = idx >> 8, n = (idx >> 3) & 31, c4 = idx & 7;
                rb[p] = *reinterpret_cast<const float4*>(
                    Bp + (size_t)g * HI + (size_t)(hBase + n) * I_DIM + kOff + c4 * 4);
            }
        }

        // ---- compute on current smem tile: 4 k-steps of 8 ----
#pragma unroll
        for (int kk = 0; kk < BK; kk += 8) {
            uint32_t af[2][4];
#pragma unroll
            for (int mi = 0; mi < 2; ++mi) {
                const int r0 = wm * 32 + mi * 16 + gid;
                af[mi][0] = As[r0][kk + tig];
                af[mi][1] = As[r0 + 8][kk + tig];
                af[mi][2] = As[r0][kk + tig + 4];
                af[mi][3] = As[r0 + 8][kk + tig + 4];
            }
            uint32_t bf[4][2][2];
#pragma unroll
            for (int g = 0; g < 4; ++g)
#pragma unroll
                for (int ni = 0; ni < 2; ++ni) {
                    const int n0 = wn * 16 + ni * 8 + gid;
                    bf[g][ni][0] = Bs[g][n0][kk + tig];
                    bf[g][ni][1] = Bs[g][n0][kk + tig + 4];
                }
#pragma unroll
            for (int g = 0; g < 4; ++g)
#pragma unroll
                for (int mi = 0; mi < 2; ++mi)
#pragma unroll
                    for (int ni = 0; ni < 2; ++ni)
                        mma_tf32(acc[g][mi][ni], af[mi], bf[g][ni]);
        }
    }

    // ---- fused LSTM epilogue ----
#pragma unroll
    for (int mi = 0; mi < 2; ++mi) {
#pragma unroll
        for (int ni = 0; ni < 2; ++ni) {
#pragma unroll
            for (int rr = 0; rr < 2; ++rr) {
#pragma unroll
                for (int cc = 0; cc < 2; ++cc) {
                    const int r = mBase + wm * 32 + mi * 16 + gid + rr * 8;
                    const int col = hBase + wn * 16 + ni * 8 + tig * 2 + cc;
                    float pre[4];
#pragma unroll
                    for (int g = 0; g < 4; ++g) {
                        pre[g] = acc[g][mi][ni][rr * 2 + cc]
                               + __ldg(&bx[g * H_DIM + col])
                               + __ldg(&bh[g * H_DIM + col]);
                    }
                    const float z  = tanhf(pre[0]);
                    const float ig = sigmoidf_fast(pre[1]);
                    const float fg = sigmoidf_fast(pre[2]);
                    const float og = sigmoidf_fast(pre[3]);
                    const float cp = __ldg(&c_prev[(size_t)r * H_DIM + col]);
                    const float cn = fg * cp + ig * z;
                    const float hn = og * tanhf(cn);
                    out[(size_t)r * H_DIM + col] = hn;
                    out[(size_t)BH + (size_t)r * H_DIM + col] = cn;
                }
            }
        }
    }
}

extern "C" void kernel_launch(void* const* d_in, const int* in_sizes, int n_in,
                              void* d_out, int out_size) {
    const float* x      = (const float*)d_in[0];
    const float* h_prev = (const float*)d_in[1];
    const float* c_prev = (const float*)d_in[2];
    const float* Wx     = (const float*)d_in[3];
    const float* bx     = (const float*)d_in[4];
    const float* Rh     = (const float*)d_in[5];
    const float* bh     = (const float*)d_in[6];
    float* out          = (float*)d_out;

    dim3 grid(H_DIM / BN, B_DIM / BM, 1);   // (32, 128)
    dim3 block(256, 1, 1);
    lstm_fused_kernel<<<grid, block>>>(x, h_prev, c_prev, Wx, bx, Rh, bh, out);
}

// round 4
// speedup vs baseline: 3.4162x; 3.4162x over previous
#include <cuda_runtime.h>
#include <cuda_fp16.h>
#include <cstdint>

// LSTM fused cell, legacy tensor path (family-target ISA only — no tcgen05).
// Prepass: fp32 -> fp16 RN, concat [x|h_prev] -> g_Ah[16384][2048],
//          [Wx|Rh] -> g_Wh[4][1024][2048].
// Main: mma.sync.m16n8k16.f16 (fp32 accum), ldmatrix.x4 fragment loads,
//       CTA tile 128(M) x 32(N) x 4 gates, BK=32, double-buffered smem,
//       fused LSTM epilogue.

#define B_DIM 16384
#define H_DIM 1024
#define K_DIM 2048
#define NKT 64          // 2048/32
#define BK 32
#define BM 128
#define BN 32           // per gate

#define PITCH 80        // bytes per smem row (32 fp16 = 64B data + 16B pad)
#define A_BYTES (BM * PITCH)            // 10240
#define B_BYTES (4 * BN * PITCH)        // 10240
#define STAGE (A_BYTES + B_BYTES)       // 20480

__device__ __half g_Ah[(size_t)B_DIM * K_DIM];       // 67 MB
__device__ __half g_Wh[(size_t)4 * H_DIM * K_DIM];   // 17 MB

__device__ __forceinline__ uint32_t smem_u32(const void* p) {
    uint32_t a;
    asm("{ .reg .u64 t; cvta.to.shared.u64 t, %1; cvt.u32.u64 %0, t; }" : "=r"(a) : "l"(p));
    return a;
}
__device__ __forceinline__ void ldsm_x4(uint32_t r[4], uint32_t addr) {
    asm volatile("ldmatrix.sync.aligned.m8n8.x4.shared.b16 {%0,%1,%2,%3}, [%4];"
                 : "=r"(r[0]), "=r"(r[1]), "=r"(r[2]), "=r"(r[3]) : "r"(addr));
}
__device__ __forceinline__ void mma_f16(float c[4], const uint32_t a[4], const uint32_t b[2]) {
    asm volatile(
        "mma.sync.aligned.m16n8k16.row.col.f32.f16.f16.f32 "
        "{%0,%1,%2,%3}, {%4,%5,%6,%7}, {%8,%9}, {%0,%1,%2,%3};"
        : "+f"(c[0]), "+f"(c[1]), "+f"(c[2]), "+f"(c[3])
        : "r"(a[0]), "r"(a[1]), "r"(a[2]), "r"(a[3]), "r"(b[0]), "r"(b[1]));
}
__device__ __forceinline__ float sigmoidf_fast(float x) {
    return 1.0f / (1.0f + __expf(-x));
}

// ================= prepass =================
#define NA8 (B_DIM * 256u)          // 4,194,304 chunks of 8 floats (A)
#define NW8 (4u * H_DIM * 256u)     // 1,048,576 chunks (W)

__global__ void __launch_bounds__(256)
prep_kernel(const float* __restrict__ x, const float* __restrict__ h_prev,
            const float* __restrict__ Wx, const float* __restrict__ Rh) {
    unsigned i = blockIdx.x * 256u + threadIdx.x;
    const float* src;
    __half* dst;
    if (i < NA8) {
        unsigned b = i >> 8, kc = i & 255;
        unsigned k0 = kc * 8;
        src = (k0 < 1024) ? x + (size_t)b * 1024 + k0
                          : h_prev + (size_t)b * 1024 + (k0 - 1024);
        dst = &g_Ah[(size_t)i * 8];
    } else {
        unsigned j = i - NA8;
        unsigned row = j >> 8, kc = j & 255;
        unsigned k0 = kc * 8;
        src = (k0 < 1024) ? Wx + (size_t)row * 1024 + k0
                          : Rh + (size_t)row * 1024 + (k0 - 1024);
        dst = &g_Wh[(size_t)j * 8];
    }
    float4 v0 = *reinterpret_cast<const float4*>(src);
    float4 v1 = *reinterpret_cast<const float4*>(src + 4);
    __half2 h0 = __floats2half2_rn(v0.x, v0.y);
    __half2 h1 = __floats2half2_rn(v0.z, v0.w);
    __half2 h2 = __floats2half2_rn(v1.x, v1.y);
    __half2 h3 = __floats2half2_rn(v1.z, v1.w);
    uint4 o = make_uint4(*(uint32_t*)&h0, *(uint32_t*)&h1, *(uint32_t*)&h2, *(uint32_t*)&h3);
    *reinterpret_cast<uint4*>(dst) = o;
}

// ================= main GEMM + fused epilogue =================
__global__ void __launch_bounds__(256, 2)
lstm_fp16_kernel(const float* __restrict__ c_prev,
                 const float* __restrict__ bx,
                 const float* __restrict__ bh,
                 float* __restrict__ out) {
    __shared__ __align__(16) uint8_t smem[2 * STAGE];

    const int t = threadIdx.x;
    const int lid = t & 31;
    const int wp = t >> 5;
    const int gid = lid >> 2;     // 0..7
    const int tig = lid & 3;      // 0..3
    const int wm = wp >> 1;       // 0..3 -> 32-row slab
    const int wn = wp & 1;        // 0..1 -> 16-col slab

    const int mBase = blockIdx.y * BM;
    const int hBase = blockIdx.x * BN;

    const uint32_t sb = smem_u32(smem);

    // Per-thread ldmatrix base offsets (byte offsets within a stage).
    // A: lane l addresses row (wm*32 + mi*16 + (l&15)), k-chunk (l>>4).
    uint32_t aOff[2];
#pragma unroll
    for (int mi = 0; mi < 2; ++mi)
        aOff[mi] = (uint32_t)((wm * 32 + mi * 16 + (lid & 15)) * PITCH + (lid >> 4) * 16);
    // B: lane l addresses n-row (wn*16 + (l>>4)*8 + (l&7)), k-chunk ((l>>3)&1).
    const uint32_t bOff = (uint32_t)(A_BYTES +
        (wn * 16 + ((lid >> 4) << 3) + (lid & 7)) * PITCH + ((lid >> 3) & 1) * 16);

    // LDG/STS mapping: idx -> (row, 16B-chunk)
    const int aRow0 = t >> 2, aC = t & 3;            // + p*64 rows
    const int bG = t >> 7, bN0 = (t >> 2) & 31, bC = t & 3;

    uint4 rA[2], rB[2];

    // ---- prologue: K-tile 0 ----
#pragma unroll
    for (int p = 0; p < 2; ++p)
        rA[p] = *reinterpret_cast<const uint4*>(
            &g_Ah[(size_t)(mBase + aRow0 + p * 64) * K_DIM + aC * 8]);
#pragma unroll
    for (int p = 0; p < 2; ++p)
        rB[p] = *reinterpret_cast<const uint4*>(
            &g_Wh[((size_t)(bG + p * 2) * H_DIM + hBase + bN0) * K_DIM + bC * 8]);

    float acc[4][2][2][4];
#pragma unroll
    for (int g = 0; g < 4; ++g)
#pragma unroll
        for (int mi = 0; mi < 2; ++mi)
#pragma unroll
            for (int ni = 0; ni < 2; ++ni)
#pragma unroll
                for (int k = 0; k < 4; ++k) acc[g][mi][ni][k] = 0.0f;

    for (int kt = 0; kt < NKT; ++kt) {
        const int buf = kt & 1;
        uint8_t* st = smem + buf * STAGE;
        const uint32_t sst = sb + buf * STAGE;

        __syncthreads();
        // ---- staged regs -> smem ----
#pragma unroll
        for (int p = 0; p < 2; ++p)
            *reinterpret_cast<uint4*>(st + (aRow0 + p * 64) * PITCH + aC * 16) = rA[p];
#pragma unroll
        for (int p = 0; p < 2; ++p)
            *reinterpret_cast<uint4*>(st + A_BYTES + ((bG + p * 2) * BN + bN0) * PITCH + bC * 16) = rB[p];
        __syncthreads();

        // ---- prefetch next K tile ----
        if (kt + 1 < NKT) {
            const int kOff = (kt + 1) * BK;
#pragma unroll
            for (int p = 0; p < 2; ++p)
                rA[p] = *reinterpret_cast<const uint4*>(
                    &g_Ah[(size_t)(mBase + aRow0 + p * 64) * K_DIM + kOff + aC * 8]);
#pragma unroll
            for (int p = 0; p < 2; ++p)
                rB[p] = *reinterpret_cast<const uint4*>(
                    &g_Wh[((size_t)(bG + p * 2) * H_DIM + hBase + bN0) * K_DIM + kOff + bC * 8]);
        }

        // ---- compute: 2 k16-steps ----
#pragma unroll
        for (int kk = 0; kk < 2; ++kk) {
            uint32_t a[2][4];
#pragma unroll
            for (int mi = 0; mi < 2; ++mi)
                ldsm_x4(a[mi], sst + aOff[mi] + kk * 32);
#pragma unroll
            for (int g = 0; g < 4; ++g) {
                uint32_t b[4];
                ldsm_x4(b, sst + bOff + g * (BN * PITCH) + kk * 32);
                mma_f16(acc[g][0][0], a[0], b + 0);
                mma_f16(acc[g][0][1], a[0], b + 2);
                mma_f16(acc[g][1][0], a[1], b + 0);
                mma_f16(acc[g][1][1], a[1], b + 2);
            }
        }
    }

    // ---- fused LSTM epilogue ----
#pragma unroll
    for (int mi = 0; mi < 2; ++mi) {
#pragma unroll
        for (int ni = 0; ni < 2; ++ni) {
#pragma unroll
            for (int rr = 0; rr < 2; ++rr) {
#pragma unroll
                for (int cc = 0; cc < 2; ++cc) {
                    const int r = mBase + wm * 32 + mi * 16 + gid + rr * 8;
                    const int col = hBase + wn * 16 + ni * 8 + tig * 2 + cc;
                    float pre[4];
#pragma unroll
                    for (int g = 0; g < 4; ++g) {
                        pre[g] = acc[g][mi][ni][rr * 2 + cc]
                               + __ldg(&bx[g * H_DIM + col])
                               + __ldg(&bh[g * H_DIM + col]);
                    }
                    const float z  = tanhf(pre[0]);
                    const float ig = sigmoidf_fast(pre[1]);
                    const float fg = sigmoidf_fast(pre[2]);
                    const float og = sigmoidf_fast(pre[3]);
                    const float cp = __ldg(&c_prev[(size_t)r * H_DIM + col]);
                    const float cn = fg * cp + ig * z;
                    const float hn = og * tanhf(cn);
                    out[(size_t)r * H_DIM + col] = hn;
                    out[(size_t)B_DIM * H_DIM + (size_t)r * H_DIM + col] = cn;
                }
            }
        }
    }
}

extern "C" void kernel_launch(void* const* d_in, const int* in_sizes, int n_in,
                              void* d_out, int out_size) {
    const float* x      = (const float*)d_in[0];
    const float* h_prev = (const float*)d_in[1];
    const float* c_prev = (const float*)d_in[2];
    const float* Wx     = (const float*)d_in[3];
    const float* bx     = (const float*)d_in[4];
    const float* Rh     = (const float*)d_in[5];
    const float* bh     = (const float*)d_in[6];
    float* out          = (float*)d_out;

    prep_kernel<<<(NA8 + NW8) / 256, 256>>>(x, h_prev, Wx, Rh);

    dim3 grid(H_DIM / BN, B_DIM / BM, 1);   // (32, 128)
    lstm_fp16_kernel<<<grid, 256>>>(c_prev, bx, bh, out);
}